// round 17
// baseline (speedup 1.0000x reference)
#include <cuda_runtime.h>
#include <cuda_bf16.h>
#include <cuda_fp16.h>
#include <cstdint>

#define B_  4
#define S_  2048
#define D_  256
#define NH_ 12

// ---- gmem scratch ----
__device__ unsigned short g_kh[(size_t)B_ * NH_ * S_ * D_];  // K  [b][n][f][d] bf16 hi
__device__ unsigned short g_kl[(size_t)B_ * NH_ * S_ * D_];  // K  lo
__device__ unsigned short g_vth[(size_t)B_ * NH_ * D_ * S_]; // 16*Vt [b][n][d][f] fp16 hi
__device__ unsigned short g_vtl[(size_t)B_ * NH_ * D_ * S_]; // 16*Vt fp16 lo
__device__ unsigned short g_xh[(size_t)B_ * S_ * D_];        // X  [b][q][d] bf16 hi
__device__ unsigned short g_xl[(size_t)B_ * S_ * D_];        // X  lo

// ---------------- helpers ----------------
__device__ __forceinline__ unsigned pack_bf16(float v0, float v1) {
    unsigned r;
    asm("cvt.rn.bf16x2.f32 %0, %1, %2;" : "=r"(r) : "f"(v1), "f"(v0));
    return r;
}
__device__ __forceinline__ unsigned pack_f16(float v0, float v1) {
    __half2 h = __halves2half2(__float2half_rn(v0), __float2half_rn(v1));
    return *(unsigned*)&h;
}
__device__ __forceinline__ float q16(float v) {
    return __half2float(__float2half_rn(v));
}
__device__ __forceinline__ unsigned long long ffma2(unsigned long long a,
                                                    unsigned long long b,
                                                    unsigned long long c) {
    unsigned long long d;
    asm("fma.rn.f32x2 %0, %1, %2, %3;" : "=l"(d) : "l"(a), "l"(b), "l"(c));
    return d;
}
__device__ __forceinline__ unsigned long long fpack2(float lo, float hi) {
    unsigned long long d;
    asm("mov.b64 %0, {%1, %2};" : "=l"(d) : "f"(lo), "f"(hi));
    return d;
}
__device__ __forceinline__ float2 funpack2(unsigned long long v) {
    float lo, hi;
    asm("mov.b64 {%0, %1}, %2;" : "=f"(lo), "=f"(hi) : "l"(v));
    return make_float2(lo, hi);
}
__device__ __forceinline__ void mma16816(float* c, const unsigned* a, const unsigned* b) {
    asm volatile(
        "mma.sync.aligned.m16n8k16.row.col.f32.bf16.bf16.f32 "
        "{%0,%1,%2,%3}, {%4,%5,%6,%7}, {%8,%9}, {%0,%1,%2,%3};"
        : "+f"(c[0]), "+f"(c[1]), "+f"(c[2]), "+f"(c[3])
        : "r"(a[0]), "r"(a[1]), "r"(a[2]), "r"(a[3]), "r"(b[0]), "r"(b[1]));
}
__device__ __forceinline__ void mma16816h(float* c, const unsigned* a, const unsigned* b) {
    asm volatile(
        "mma.sync.aligned.m16n8k16.row.col.f32.f16.f16.f32 "
        "{%0,%1,%2,%3}, {%4,%5,%6,%7}, {%8,%9}, {%0,%1,%2,%3};"
        : "+f"(c[0]), "+f"(c[1]), "+f"(c[2]), "+f"(c[3])
        : "r"(a[0]), "r"(a[1]), "r"(a[2]), "r"(a[3]), "r"(b[0]), "r"(b[1]));
}

// ---------------- projection: smem-staged epilogue ----------------
#define OSTR 132
#define VSCALE 16.0f
__global__ __launch_bounds__(256, 2)
void proj_kernel(const float* __restrict__ X,
                 const float* __restrict__ Wqk, const float* __restrict__ bqk,
                 const float* __restrict__ Wv,  const float* __restrict__ bvp)
{
    const float* W    = (blockIdx.z == 0) ? Wqk : Wv;
    const float* bias = (blockIdx.z == 0) ? bqk : bvp;

    extern __shared__ float psm[];
    float (*As)[128] = (float(*)[128])psm;
    float (*Bs)[128] = (float(*)[128])(psm + 1024);
    float* outs = psm;

    const int t  = threadIdx.x;
    const int tx = t & 15, ty = t >> 4;
    const int m0 = blockIdx.y * 128;
    const int c0 = blockIdx.x * 128;

    unsigned long long acc[8][4];
#pragma unroll
    for (int i = 0; i < 8; i++)
#pragma unroll
        for (int j = 0; j < 4; j++) acc[i][j] = 0ull;

    const int lm = t >> 1, lk = (t & 1) * 4;
    const int brow = t >> 5, bcol = (t & 31) * 4;

    for (int k0 = 0; k0 < 256; k0 += 8) {
        float4 xa = *(const float4*)&X[(size_t)(m0 + lm) * 256 + k0 + lk];
        float4 wb = *(const float4*)&W[(size_t)(k0 + brow) * 3072 + c0 + bcol];
        __syncthreads();
        As[lk + 0][lm] = xa.x; As[lk + 1][lm] = xa.y;
        As[lk + 2][lm] = xa.z; As[lk + 3][lm] = xa.w;
        *(float4*)&Bs[brow][bcol] = wb;
        __syncthreads();
#pragma unroll
        for (int kk = 0; kk < 8; kk++) {
            float a[8];
            *(float4*)&a[0] = *(const float4*)&As[kk][ty * 8];
            *(float4*)&a[4] = *(const float4*)&As[kk][ty * 8 + 4];
            ulonglong2 b01 = *(const ulonglong2*)&Bs[kk][tx * 8];
            ulonglong2 b23 = *(const ulonglong2*)&Bs[kk][tx * 8 + 4];
            unsigned long long bp[4] = {b01.x, b01.y, b23.x, b23.y};
#pragma unroll
            for (int i = 0; i < 8; i++) {
                unsigned long long ap = fpack2(a[i], a[i]);
#pragma unroll
                for (int j = 0; j < 4; j++) acc[i][j] = ffma2(ap, bp[j], acc[i][j]);
            }
        }
    }
    __syncthreads();

#pragma unroll
    for (int j = 0; j < 4; j++) {
        int cl = tx * 8 + 2 * j;
        float2 bv2 = *(const float2*)&bias[c0 + cl];
#pragma unroll
        for (int i = 0; i < 8; i++) {
            float2 v = funpack2(acc[i][j]);
            v.x += bv2.x; v.y += bv2.y;
            *(float2*)&outs[(ty * 8 + i) * OSTR + cl] = v;
        }
    }
    __syncthreads();

    const int nh = c0 >> 8;
    const int d0 = c0 & 255;
    const int bb = m0 >> 11;
    const int fb = m0 & 2047;

    if (blockIdx.z == 0) {
        // K (bf16 hi/lo): rows f, cols d contiguous
        const int i = t >> 1, seg = t & 1;
        size_t base = ((size_t)(bb * NH_ + nh) * S_ + fb + i) * D_ + d0 + seg * 64;
        const float* srow = &outs[i * OSTR + seg * 64];
#pragma unroll
        for (int u = 0; u < 8; u++) {
            unsigned hi[4], lo[4];
#pragma unroll
            for (int e = 0; e < 4; e++) {
                float a = srow[u * 8 + 2 * e], b = srow[u * 8 + 2 * e + 1];
                float ha = __bfloat162float(__float2bfloat16(a));
                float hb = __bfloat162float(__float2bfloat16(b));
                hi[e] = pack_bf16(ha, hb);
                lo[e] = pack_bf16(a - ha, b - hb);
            }
            *(uint4*)&g_kh[base + u * 8] = *(uint4*)hi;
            *(uint4*)&g_kl[base + u * 8] = *(uint4*)lo;
        }
    } else {
        // 16*Vt (fp16 hi/lo): rows d, cols f contiguous
        const int j = t >> 1, seg = t & 1;
        size_t base = ((size_t)(bb * NH_ + nh) * D_ + d0 + j) * S_ + fb + seg * 64;
        const float* scol = &outs[(seg * 64) * OSTR + j];
#pragma unroll
        for (int u = 0; u < 8; u++) {
            unsigned hi[4], lo[4];
#pragma unroll
            for (int e = 0; e < 4; e++) {
                float a = scol[(u * 8 + 2 * e) * OSTR] * VSCALE;
                float b = scol[(u * 8 + 2 * e + 1) * OSTR] * VSCALE;
                float ha = q16(a), hb = q16(b);
                hi[e] = pack_f16(ha, hb);
                lo[e] = pack_f16(a - ha, b - hb);
            }
            *(uint4*)&g_vth[base + u * 8] = *(uint4*)hi;
            *(uint4*)&g_vtl[base + u * 8] = *(uint4*)lo;
        }
    }
}

// ---------------- X -> bf16 hi/lo ----------------
__global__ __launch_bounds__(256, 4)
void conv_x_kernel(const float* __restrict__ X)
{
    const int gid = blockIdx.x * 256 + threadIdx.x;
    const size_t base = (size_t)gid * 8;
    float f[8];
    *(float4*)&f[0] = *(const float4*)&X[base];
    *(float4*)&f[4] = *(const float4*)&X[base + 4];
    unsigned hi[4], lo[4];
#pragma unroll
    for (int e = 0; e < 4; e++) {
        float a = f[2 * e], b = f[2 * e + 1];
        float ha = __bfloat162float(__float2bfloat16(a));
        float hb = __bfloat162float(__float2bfloat16(b));
        hi[e] = pack_bf16(ha, hb);
        lo[e] = pack_bf16(a - ha, b - hb);
    }
    *(uint4*)&g_xh[base] = *(uint4*)hi;
    *(uint4*)&g_xl[base] = *(uint4*)lo;
}

// ---------------- attention: online-max softmax, fp16 PV ----------------
#define XH_ 0
#define XL_ 33792
#define KH_ 67584
#define KL_ 76032
#define VH_ 84480
#define VL_ 94720
#define SMT (104960 * 2)
#define XSTR 264
#define VSTR 40
#define PSCALE 16384.0f

__global__ __launch_bounds__(256, 1)
void attn_kernel(const int* __restrict__ mask, float* __restrict__ out)
{
    extern __shared__ unsigned short s16[];
    const int t = threadIdx.x;
    const int w = t >> 5, lane = t & 31;
    const int g = lane >> 2, m4 = lane & 3;
    const int qt = blockIdx.x, nh = blockIdx.y, bb = blockIdx.z;

    // ---- load X tile (128 x 256) hi+lo ----
    {
        const uint4* sxh = (const uint4*)(g_xh + ((size_t)(bb * S_ + qt * 128)) * 256);
        const uint4* sxl = (const uint4*)(g_xl + ((size_t)(bb * S_ + qt * 128)) * 256);
        uint4* dh = (uint4*)(s16 + XH_);
        uint4* dl = (uint4*)(s16 + XL_);
#pragma unroll
        for (int i = 0; i < 16; i++) {
            int id = i * 256 + t;
            int row = id >> 5, c = id & 31;
            dh[row * 33 + c] = sxh[id];
            dl[row * 33 + c] = sxl[id];
        }
    }

    float oa[32][4];
#pragma unroll
    for (int j = 0; j < 32; j++)
#pragma unroll
        for (int e = 0; e < 4; e++) oa[j][e] = 0.0f;
    float l0 = 0.0f, l1 = 0.0f;
    float m0r = -3.4e38f, m1r = -3.4e38f;

    const size_t kvbase = (size_t)(bb * NH_ + nh);
    const unsigned short* gk_h = g_kh + kvbase * S_ * D_;
    const unsigned short* gk_l = g_kl + kvbase * S_ * D_;
    const unsigned short* gv_h = g_vth + kvbase * D_ * S_;
    const unsigned short* gv_l = g_vtl + kvbase * D_ * S_;
    const int* mrow0 = mask + ((size_t)bb * S_ + qt * 128 + w * 16 + g) * S_;
    const int* mrow1 = mrow0 + 8 * S_;

    for (int kt = 0; kt < 64; kt++) {
        const int f0 = kt * 32;
        __syncthreads();
        // ---- load K tile (32 x 256) hi+lo ----
        {
            const uint4* skh = (const uint4*)(gk_h + (size_t)f0 * 256);
            const uint4* skl = (const uint4*)(gk_l + (size_t)f0 * 256);
            uint4* dh = (uint4*)(s16 + KH_);
            uint4* dl = (uint4*)(s16 + KL_);
#pragma unroll
            for (int i = 0; i < 4; i++) {
                int id = i * 256 + t;
                int row = id >> 5, c = id & 31;
                dh[row * 33 + c] = skh[id];
                dl[row * 33 + c] = skl[id];
            }
        }
        // ---- load Vt tile (256 x 32) hi+lo ----
        {
            const uint4* svh = (const uint4*)gv_h;
            const uint4* svl = (const uint4*)gv_l;
            uint4* dh = (uint4*)(s16 + VH_);
            uint4* dl = (uint4*)(s16 + VL_);
            const int fo = f0 >> 3;
#pragma unroll
            for (int i = 0; i < 4; i++) {
                int id = i * 256 + t;
                int row = id >> 2, c = id & 3;
                dh[row * 5 + c] = svh[(row << 8) + fo + c];
                dl[row * 5 + c] = svl[(row << 8) + fo + c];
            }
        }
        __syncthreads();

        // ---- S = X . K^T : dual accumulator banks ----
        float sa[4][4], sb[4][4];
#pragma unroll
        for (int j = 0; j < 4; j++)
#pragma unroll
            for (int e = 0; e < 4; e++) { sa[j][e] = 0.0f; sb[j][e] = 0.0f; }

#pragma unroll
        for (int ks = 0; ks < 16; ks++) {
            const int kc = ks * 16 + 2 * m4;
            unsigned ah[4], al[4];
            ah[0] = *(const unsigned*)&s16[XH_ + (w * 16 + g) * XSTR + kc];
            ah[1] = *(const unsigned*)&s16[XH_ + (w * 16 + g + 8) * XSTR + kc];
            ah[2] = *(const unsigned*)&s16[XH_ + (w * 16 + g) * XSTR + kc + 8];
            ah[3] = *(const unsigned*)&s16[XH_ + (w * 16 + g + 8) * XSTR + kc + 8];
            al[0] = *(const unsigned*)&s16[XL_ + (w * 16 + g) * XSTR + kc];
            al[1] = *(const unsigned*)&s16[XL_ + (w * 16 + g + 8) * XSTR + kc];
            al[2] = *(const unsigned*)&s16[XL_ + (w * 16 + g) * XSTR + kc + 8];
            al[3] = *(const unsigned*)&s16[XL_ + (w * 16 + g + 8) * XSTR + kc + 8];
            unsigned bh[4][2], bl[4][2];
#pragma unroll
            for (int j = 0; j < 4; j++) {
                bh[j][0] = *(const unsigned*)&s16[KH_ + (8 * j + g) * XSTR + kc];
                bh[j][1] = *(const unsigned*)&s16[KH_ + (8 * j + g) * XSTR + kc + 8];
                bl[j][0] = *(const unsigned*)&s16[KL_ + (8 * j + g) * XSTR + kc];
                bl[j][1] = *(const unsigned*)&s16[KL_ + (8 * j + g) * XSTR + kc + 8];
            }
            float (*acc)[4] = (ks & 1) ? sb : sa;
#pragma unroll
            for (int j = 0; j < 4; j++) mma16816(acc[j], ah, bh[j]);
#pragma unroll
            for (int j = 0; j < 4; j++) mma16816(acc[j], al, bh[j]);
#pragma unroll
            for (int j = 0; j < 4; j++) mma16816(acc[j], ah, bl[j]);
        }

        // ---- online-max softmax (fp16 P, PSCALE) ----
        float mloc0 = -3.4e38f, mloc1 = -3.4e38f;
#pragma unroll
        for (int j = 0; j < 4; j++) {
            int2 mv0 = *(const int2*)&mrow0[f0 + 8 * j + 2 * m4];
            int2 mv1 = *(const int2*)&mrow1[f0 + 8 * j + 2 * m4];
            sa[j][0] += sb[j][0] + (1.0f - (float)mv0.x) * -10000.0f;
            sa[j][1] += sb[j][1] + (1.0f - (float)mv0.y) * -10000.0f;
            sa[j][2] += sb[j][2] + (1.0f - (float)mv1.x) * -10000.0f;
            sa[j][3] += sb[j][3] + (1.0f - (float)mv1.y) * -10000.0f;
            mloc0 = fmaxf(mloc0, fmaxf(sa[j][0], sa[j][1]));
            mloc1 = fmaxf(mloc1, fmaxf(sa[j][2], sa[j][3]));
        }
        mloc0 = fmaxf(mloc0, __shfl_xor_sync(0xffffffffu, mloc0, 1));
        mloc0 = fmaxf(mloc0, __shfl_xor_sync(0xffffffffu, mloc0, 2));
        mloc1 = fmaxf(mloc1, __shfl_xor_sync(0xffffffffu, mloc1, 1));
        mloc1 = fmaxf(mloc1, __shfl_xor_sync(0xffffffffu, mloc1, 2));
        const float mn0 = fmaxf(m0r, mloc0), mn1 = fmaxf(m1r, mloc1);
        const float sc0 = __expf(m0r - mn0), sc1 = __expf(m1r - mn1);
        m0r = mn0; m1r = mn1;
        if (sc0 != 1.0f || sc1 != 1.0f) {
            l0 *= sc0; l1 *= sc1;
#pragma unroll
            for (int j = 0; j < 32; j++) {
                oa[j][0] *= sc0; oa[j][1] *= sc0;
                oa[j][2] *= sc1; oa[j][3] *= sc1;
            }
        }
        float p[4][4];
#pragma unroll
        for (int j = 0; j < 4; j++) {
            p[j][0] = q16(__expf(sa[j][0] - mn0) * PSCALE);
            p[j][1] = q16(__expf(sa[j][1] - mn0) * PSCALE);
            p[j][2] = q16(__expf(sa[j][2] - mn1) * PSCALE);
            p[j][3] = q16(__expf(sa[j][3] - mn1) * PSCALE);
            l0 += p[j][0] + p[j][1];
            l1 += p[j][2] + p[j][3];
        }

        // ---- O += Ph . (Vh + Vl)  (fp16, 2 MMAs per B-tile) ----
#pragma unroll
        for (int s = 0; s < 2; s++) {
            unsigned pah[4];
            pah[0] = pack_f16(p[2 * s][0], p[2 * s][1]);
            pah[1] = pack_f16(p[2 * s][2], p[2 * s][3]);
            pah[2] = pack_f16(p[2 * s + 1][0], p[2 * s + 1][1]);
            pah[3] = pack_f16(p[2 * s + 1][2], p[2 * s + 1][3]);
            const int kc = s * 16 + 2 * m4;
#pragma unroll
            for (int j = 0; j < 32; j++) {
                unsigned bvh[2], bvl[2];
                bvh[0] = *(const unsigned*)&s16[VH_ + (8 * j + g) * VSTR + kc];
                bvh[1] = *(const unsigned*)&s16[VH_ + (8 * j + g) * VSTR + kc + 8];
                bvl[0] = *(const unsigned*)&s16[VL_ + (8 * j + g) * VSTR + kc];
                bvl[1] = *(const unsigned*)&s16[VL_ + (8 * j + g) * VSTR + kc + 8];
                mma16816h(oa[j], pah, bvh);
                mma16816h(oa[j], pah, bvl);
            }
        }
    }

    // ---- epilogue: divide by 16*l (VSCALE folds in), atomic head-sum ----
    l0 += __shfl_xor_sync(0xffffffffu, l0, 1);
    l0 += __shfl_xor_sync(0xffffffffu, l0, 2);
    l1 += __shfl_xor_sync(0xffffffffu, l1, 1);
    l1 += __shfl_xor_sync(0xffffffffu, l1, 2);
    const float inv0 = 1.0f / (VSCALE * l0), inv1 = 1.0f / (VSCALE * l1);

    const int row0 = qt * 128 + w * 16 + g;
    float* o0 = out + ((size_t)bb * S_ + row0) * D_;
    float* o1 = o0 + 8 * D_;
#pragma unroll
    for (int j = 0; j < 32; j++) {
        int c = 8 * j + 2 * m4;
        float2 v0 = make_float2(oa[j][0] * inv0, oa[j][1] * inv0);
        float2 v1 = make_float2(oa[j][2] * inv1, oa[j][3] * inv1);
        atomicAdd((float2*)&o0[c], v0);
        atomicAdd((float2*)&o1[c], v1);
    }
}

// ---------------- launch ----------------
extern "C" void kernel_launch(void* const* d_in, const int* in_sizes, int n_in,
                              void* d_out, int out_size)
{
    (void)in_sizes; (void)n_in;
    const float* X   = (const float*)d_in[0];
    const int*   msk = (const int*)  d_in[1];
    const float* Wqk = (const float*)d_in[2];
    const float* bqk = (const float*)d_in[3];
    const float* Wv  = (const float*)d_in[4];
    const float* bv  = (const float*)d_in[5];
    float* out = (float*)d_out;

    cudaMemsetAsync(out, 0, (size_t)out_size * sizeof(float), 0);

    conv_x_kernel<<<(B_ * S_ * D_) / (8 * 256), 256>>>(X);

    const int proj_smem = 128 * OSTR * (int)sizeof(float);
    cudaFuncSetAttribute(proj_kernel,
                         cudaFuncAttributeMaxDynamicSharedMemorySize, proj_smem);
    dim3 pg(3072 / 128, (B_ * S_) / 128, 2);
    proj_kernel<<<pg, 256, proj_smem>>>(X, Wqk, bqk, Wv, bv);

    cudaFuncSetAttribute(attn_kernel,
                         cudaFuncAttributeMaxDynamicSharedMemorySize, SMT);
    dim3 ag(16, NH_, B_);
    attn_kernel<<<ag, 256, SMT>>>(msk, out);
}